// round 1
// baseline (speedup 1.0000x reference)
#include <cuda_runtime.h>
#include <cuda_bf16.h>

// Problem constants
#define B_ROWS   16384
#define K_FEATS  32
#define H_DIM    256
#define FULLMASK 0xFFFFFFFFu

// Tile of rows per block
#define TILE     16

// Scratch: fc1_w transposed to [iq][j] float4 layout (iq = i/4 over 512 inputs, j = 0..31 outputs)
__device__ float4 g_fc1T[128 * 32];

__global__ void prep_fc1(const float* __restrict__ fc1_w) {
    int t = blockIdx.x * blockDim.x + threadIdx.x;
    if (t < 128 * 32) {
        int iq = t >> 5;
        int j  = t & 31;
        const float* p = fc1_w + j * 512 + iq * 4;
        g_fc1T[t] = make_float4(p[0], p[1], p[2], p[3]);
    }
}

__device__ __forceinline__ float4 clip01(float4 v) {
    v.x = fminf(fmaxf(v.x, 0.0f), 1.0f);
    v.y = fminf(fmaxf(v.y, 0.0f), 1.0f);
    v.z = fminf(fmaxf(v.z, 0.0f), 1.0f);
    v.w = fminf(fmaxf(v.w, 0.0f), 1.0f);
    return v;
}

__device__ __forceinline__ void fma4(float4& a, float m, const float4& w) {
    a.x = fmaf(m, w.x, a.x);
    a.y = fmaf(m, w.y, a.y);
    a.z = fmaf(m, w.z, a.z);
    a.w = fmaf(m, w.w, a.w);
}

__global__ __launch_bounds__(128)
void nnue_kernel(const int*   __restrict__ wft_ics,
                 const float* __restrict__ wft_vals,
                 const int*   __restrict__ bft_ics,
                 const float* __restrict__ bft_vals,
                 const int*   __restrict__ stm,
                 const float* __restrict__ ft_w,
                 const float* __restrict__ ft_b,
                 const float* __restrict__ fc1_b,
                 const float* __restrict__ fc2_w,
                 const float* __restrict__ fc2_b,
                 const float* __restrict__ fco_w,
                 const float* __restrict__ fco_b,
                 float*       __restrict__ out)
{
    __shared__ float4 xs[TILE * 128];   // per-row x[512] as 128 float4, 32 KB
    __shared__ float  fc2T[32 * 32];    // fc2T[i*32+j] = fc2_w[j][i], conflict-free for lane j

    const int tid  = threadIdx.x;
    const int lane = tid & 31;
    const int warp = tid >> 5;
    const int row0 = blockIdx.x * TILE;

    // Load fc2 transposed into shared (coalesced read of fc2_w)
    for (int idx = tid; idx < 1024; idx += 128) {
        // idx = j*32 + i  ->  fc2T[i*32 + j]
        fc2T[(idx & 31) * 32 + (idx >> 5)] = fc2_w[idx];
    }

    // Per-lane ft bias (8 columns)
    const float4 bias0 = *(const float4*)(ft_b + lane * 8);
    const float4 bias1 = *(const float4*)(ft_b + lane * 8 + 4);

    // ---------------- Phase 1: gather (1 warp per row, 4 rows per warp) -------------
    #pragma unroll
    for (int r = 0; r < 4; r++) {
        const int rloc = warp * 4 + r;
        const int row  = row0 + rloc;
        const int base = row * K_FEATS + lane;

        const int   wi = wft_ics[base];
        const float wv = wft_vals[base];
        const int   bi = bft_ics[base];
        const float bv = bft_vals[base];

        float4 aw0 = bias0, aw1 = bias1;
        float4 ab0 = bias0, ab1 = bias1;

        #pragma unroll 4
        for (int k = 0; k < 32; k++) {
            const int   iw = __shfl_sync(FULLMASK, wi, k);
            const float vw = __shfl_sync(FULLMASK, wv, k);
            const int   ib = __shfl_sync(FULLMASK, bi, k);
            const float vb = __shfl_sync(FULLMASK, bv, k);

            const float mw = (iw >= 0) ? vw : 0.0f;
            const float mb = (ib >= 0) ? vb : 0.0f;
            const int   sw = (iw >= 0) ? iw : 0;
            const int   sb = (ib >= 0) ? ib : 0;

            const float4* pw = (const float4*)(ft_w + (size_t)sw * H_DIM) + lane * 2;
            const float4* pb = (const float4*)(ft_w + (size_t)sb * H_DIM) + lane * 2;
            const float4 w0 = __ldg(pw);
            const float4 w1 = __ldg(pw + 1);
            const float4 b0 = __ldg(pb);
            const float4 b1 = __ldg(pb + 1);

            fma4(aw0, mw, w0); fma4(aw1, mw, w1);
            fma4(ab0, mb, b0); fma4(ab1, mb, b1);
        }

        // stm-conditional swap + clip
        const int s = stm[row];
        float4 lo0, lo1, hi0, hi1;
        if (s) { lo0 = ab0; lo1 = ab1; hi0 = aw0; hi1 = aw1; }
        else   { lo0 = aw0; lo1 = aw1; hi0 = ab0; hi1 = ab1; }
        lo0 = clip01(lo0); lo1 = clip01(lo1);
        hi0 = clip01(hi0); hi1 = clip01(hi1);

        float4* xr = xs + rloc * 128;
        xr[lane * 2]          = lo0;
        xr[lane * 2 + 1]      = lo1;
        xr[64 + lane * 2]     = hi0;
        xr[64 + lane * 2 + 1] = hi1;
    }

    __syncthreads();

    // ---------------- Phase 2: FC1 (lane j = output j, 4 rows per warp) -------------
    const int j = lane;
    const float b1j = fc1_b[j];
    float h1[4] = { b1j, b1j, b1j, b1j };

    const float4* xbase = xs + (warp * 4) * 128;

    #pragma unroll 4
    for (int iq = 0; iq < 128; iq++) {
        const float4 w = g_fc1T[iq * 32 + j];   // coalesced 512B warp request, L1-hot
        #pragma unroll
        for (int r = 0; r < 4; r++) {
            const float4 xv = xbase[r * 128 + iq];   // broadcast LDS
            h1[r] = fmaf(w.x, xv.x,
                    fmaf(w.y, xv.y,
                    fmaf(w.z, xv.z,
                    fmaf(w.w, xv.w, h1[r]))));
        }
    }

    // ---------------- FC2 + output head ----------------------------------------------
    const float b2j = fc2_b[j];
    const float fcw = fco_w[j];
    const float fcb = __ldg(fco_b);

    #pragma unroll
    for (int r = 0; r < 4; r++) {
        float h = fminf(fmaxf(h1[r], 0.0f), 1.0f);
        float h2 = b2j;
        #pragma unroll
        for (int i = 0; i < 32; i++) {
            h2 = fmaf(fc2T[i * 32 + j], __shfl_sync(FULLMASK, h, i), h2);
        }
        h2 = fminf(fmaxf(h2, 0.0f), 1.0f);

        float o = h2 * fcw;
        #pragma unroll
        for (int off = 16; off; off >>= 1)
            o += __shfl_xor_sync(FULLMASK, o, off);

        if (lane == 0)
            out[row0 + warp * 4 + r] = o + fcb;
    }
}

extern "C" void kernel_launch(void* const* d_in, const int* in_sizes, int n_in,
                              void* d_out, int out_size)
{
    const int*   wft_ics  = (const int*)  d_in[0];
    const float* wft_vals = (const float*)d_in[1];
    const int*   bft_ics  = (const int*)  d_in[2];
    const float* bft_vals = (const float*)d_in[3];
    const int*   stm      = (const int*)  d_in[4];
    const float* ft_w     = (const float*)d_in[5];
    const float* ft_b     = (const float*)d_in[6];
    const float* fc1_w    = (const float*)d_in[7];
    const float* fc1_b    = (const float*)d_in[8];
    const float* fc2_w    = (const float*)d_in[9];
    const float* fc2_b    = (const float*)d_in[10];
    const float* fco_w    = (const float*)d_in[11];
    const float* fco_b    = (const float*)d_in[12];
    float* out = (float*)d_out;

    prep_fc1<<<32, 128>>>(fc1_w);
    nnue_kernel<<<B_ROWS / TILE, 128>>>(wft_ics, wft_vals, bft_ics, bft_vals, stm,
                                        ft_w, ft_b, fc1_b, fc2_w, fc2_b,
                                        fco_w, fco_b, out);
}

// round 2
// speedup vs baseline: 1.4687x; 1.4687x over previous
#include <cuda_runtime.h>
#include <cuda_fp16.h>

// Problem constants
#define B_ROWS   16384
#define K_FEATS  32
#define H_DIM    256
#define FULLMASK 0xFFFFFFFFu

// Tile of rows per block
#define TILE     16

// fp16 copy of ft_w: 40960 rows x 256 cols = 10.49M halves = 20MB (128 half2 per row)
__device__ __half2 g_ftw_h[40960 * 128];

// fc1_w transposed to [iq][j] float4 layout (iq = i/4 over 512 inputs, j = 0..31 outputs)
__device__ float4 g_fc1T[128 * 32];

// ---- prep: fp32 -> fp16 table conversion (one float4 -> two half2 per thread) ----
__global__ void prep_ftw(const float* __restrict__ ft_w) {
    int i = blockIdx.x * blockDim.x + threadIdx.x;   // over 2,621,440 float4 chunks
    const float4 v = __ldg((const float4*)ft_w + i);
    g_ftw_h[i * 2]     = __floats2half2_rn(v.x, v.y);
    g_ftw_h[i * 2 + 1] = __floats2half2_rn(v.z, v.w);
}

__global__ void prep_fc1(const float* __restrict__ fc1_w) {
    int t = blockIdx.x * blockDim.x + threadIdx.x;
    if (t < 128 * 32) {
        int iq = t >> 5;
        int j  = t & 31;
        const float* p = fc1_w + j * 512 + iq * 4;
        g_fc1T[t] = make_float4(p[0], p[1], p[2], p[3]);
    }
}

__device__ __forceinline__ float4 clip01(float4 v) {
    v.x = fminf(fmaxf(v.x, 0.0f), 1.0f);
    v.y = fminf(fmaxf(v.y, 0.0f), 1.0f);
    v.z = fminf(fmaxf(v.z, 0.0f), 1.0f);
    v.w = fminf(fmaxf(v.w, 0.0f), 1.0f);
    return v;
}

// accumulate 8 fp16 values (one uint4) scaled by m into two float4 accumulators
__device__ __forceinline__ void acc8(float4& a0, float4& a1, float m, uint4 r) {
    const __half2* h = (const __half2*)&r;
    float2 f0 = __half22float2(h[0]);
    float2 f1 = __half22float2(h[1]);
    float2 f2 = __half22float2(h[2]);
    float2 f3 = __half22float2(h[3]);
    a0.x = fmaf(m, f0.x, a0.x);  a0.y = fmaf(m, f0.y, a0.y);
    a0.z = fmaf(m, f1.x, a0.z);  a0.w = fmaf(m, f1.y, a0.w);
    a1.x = fmaf(m, f2.x, a1.x);  a1.y = fmaf(m, f2.y, a1.y);
    a1.z = fmaf(m, f3.x, a1.z);  a1.w = fmaf(m, f3.y, a1.w);
}

__device__ __forceinline__ uint4 pack8(float4 a, float4 b) {
    uint4 r;
    __half2 h0 = __floats2half2_rn(a.x, a.y);
    __half2 h1 = __floats2half2_rn(a.z, a.w);
    __half2 h2 = __floats2half2_rn(b.x, b.y);
    __half2 h3 = __floats2half2_rn(b.z, b.w);
    r.x = *(unsigned*)&h0; r.y = *(unsigned*)&h1;
    r.z = *(unsigned*)&h2; r.w = *(unsigned*)&h3;
    return r;
}

__global__ __launch_bounds__(128, 8)
void nnue_kernel(const int*   __restrict__ wft_ics,
                 const float* __restrict__ wft_vals,
                 const int*   __restrict__ bft_ics,
                 const float* __restrict__ bft_vals,
                 const int*   __restrict__ stm,
                 const float* __restrict__ ft_b,
                 const float* __restrict__ fc1_b,
                 const float* __restrict__ fc2_w,
                 const float* __restrict__ fc2_b,
                 const float* __restrict__ fco_w,
                 const float* __restrict__ fco_b,
                 float*       __restrict__ out)
{
    __shared__ __half2 xs[TILE * 256];  // per-row x[512] as fp16, 1KB/row, 16KB
    __shared__ float   fc2T[32 * 32];   // fc2T[i*32+j] = fc2_w[j][i]

    const int tid  = threadIdx.x;
    const int lane = tid & 31;
    const int warp = tid >> 5;
    const int row0 = blockIdx.x * TILE;

    for (int idx = tid; idx < 1024; idx += 128)
        fc2T[(idx & 31) * 32 + (idx >> 5)] = fc2_w[idx];

    // Per-lane ft bias (8 columns: lane*8 .. lane*8+7)
    const float4 bias0 = *(const float4*)(ft_b + lane * 8);
    const float4 bias1 = *(const float4*)(ft_b + lane * 8 + 4);

    // ---------------- Phase 1: gather (1 warp per row, 4 rows per warp) -------------
    #pragma unroll
    for (int r = 0; r < 4; r++) {
        const int rloc = warp * 4 + r;
        const int row  = row0 + rloc;
        const int base = row * K_FEATS + lane;

        const int   wi = __ldg(wft_ics + base);
        const float wv = __ldg(wft_vals + base);
        const int   bi = __ldg(bft_ics + base);
        const float bv = __ldg(bft_vals + base);

        float4 aw0 = bias0, aw1 = bias1;
        float4 ab0 = bias0, ab1 = bias1;

        #pragma unroll 4
        for (int k = 0; k < 32; k++) {
            const int   iw = __shfl_sync(FULLMASK, wi, k);
            const float vw = __shfl_sync(FULLMASK, wv, k);
            const int   ib = __shfl_sync(FULLMASK, bi, k);
            const float vb = __shfl_sync(FULLMASK, bv, k);

            const float mw = (iw >= 0) ? vw : 0.0f;
            const float mb = (ib >= 0) ? vb : 0.0f;
            const int   sw = (iw >= 0) ? iw : 0;
            const int   sb = (ib >= 0) ? ib : 0;

            // one uint4 (8 halves = cols lane*8..lane*8+7) per feature row
            const uint4 rw = __ldg((const uint4*)(g_ftw_h + (size_t)sw * 128) + lane);
            const uint4 rb = __ldg((const uint4*)(g_ftw_h + (size_t)sb * 128) + lane);

            acc8(aw0, aw1, mw, rw);
            acc8(ab0, ab1, mb, rb);
        }

        // stm-conditional swap + clip
        const int s = __ldg(stm + row);
        float4 lo0, lo1, hi0, hi1;
        if (s) { lo0 = ab0; lo1 = ab1; hi0 = aw0; hi1 = aw1; }
        else   { lo0 = aw0; lo1 = aw1; hi0 = ab0; hi1 = ab1; }
        lo0 = clip01(lo0); lo1 = clip01(lo1);
        hi0 = clip01(hi0); hi1 = clip01(hi1);

        // store as fp16: row layout = 512 halves (256 half2); lane owns 16B chunks
        uint4* xr = (uint4*)(xs + rloc * 256);
        xr[lane]      = pack8(lo0, lo1);
        xr[32 + lane] = pack8(hi0, hi1);
    }

    __syncthreads();

    // ---------------- Phase 2: FC1 (lane j = output j, 4 rows per warp) -------------
    const int j = lane;
    const float b1j = __ldg(fc1_b + j);
    float h1[4] = { b1j, b1j, b1j, b1j };

    const __half2* xbase = xs + (warp * 4) * 256;

    #pragma unroll 4
    for (int iq = 0; iq < 128; iq++) {
        const float4 w = g_fc1T[iq * 32 + j];   // coalesced 512B warp request, L1-hot
        #pragma unroll
        for (int r = 0; r < 4; r++) {
            // inputs 4*iq .. 4*iq+3 = two half2, broadcast LDS.64
            const uint2 xv = ((const uint2*)(xbase + r * 256))[iq];
            const float2 fa = __half22float2(*(const __half2*)&xv.x);
            const float2 fb = __half22float2(*(const __half2*)&xv.y);
            h1[r] = fmaf(w.x, fa.x,
                    fmaf(w.y, fa.y,
                    fmaf(w.z, fb.x,
                    fmaf(w.w, fb.y, h1[r]))));
        }
    }

    // ---------------- FC2 + output head ----------------------------------------------
    const float b2j = __ldg(fc2_b + j);
    const float fcw = __ldg(fco_w + j);
    const float fcb = __ldg(fco_b);

    #pragma unroll
    for (int r = 0; r < 4; r++) {
        float h = fminf(fmaxf(h1[r], 0.0f), 1.0f);
        float h2 = b2j;
        #pragma unroll
        for (int i = 0; i < 32; i++) {
            h2 = fmaf(fc2T[i * 32 + j], __shfl_sync(FULLMASK, h, i), h2);
        }
        h2 = fminf(fmaxf(h2, 0.0f), 1.0f);

        float o = h2 * fcw;
        #pragma unroll
        for (int off = 16; off; off >>= 1)
            o += __shfl_xor_sync(FULLMASK, o, off);

        if (lane == 0)
            out[row0 + warp * 4 + r] = o + fcb;
    }
}

extern "C" void kernel_launch(void* const* d_in, const int* in_sizes, int n_in,
                              void* d_out, int out_size)
{
    const int*   wft_ics  = (const int*)  d_in[0];
    const float* wft_vals = (const float*)d_in[1];
    const int*   bft_ics  = (const int*)  d_in[2];
    const float* bft_vals = (const float*)d_in[3];
    const int*   stm      = (const int*)  d_in[4];
    const float* ft_w     = (const float*)d_in[5];
    const float* ft_b     = (const float*)d_in[6];
    const float* fc1_w    = (const float*)d_in[7];
    const float* fc1_b    = (const float*)d_in[8];
    const float* fc2_w    = (const float*)d_in[9];
    const float* fc2_b    = (const float*)d_in[10];
    const float* fco_w    = (const float*)d_in[11];
    const float* fco_b    = (const float*)d_in[12];
    float* out = (float*)d_out;

    // 40960*256/4 = 2,621,440 float4 chunks; 10240 blocks x 256 threads
    prep_ftw<<<10240, 256>>>(ft_w);
    prep_fc1<<<32, 128>>>(fc1_w);
    nnue_kernel<<<B_ROWS / TILE, 128>>>(wft_ics, wft_vals, bft_ics, bft_vals, stm,
                                        ft_b, fc1_b, fc2_w, fc2_b,
                                        fco_w, fco_b, out);
}